// round 1
// baseline (speedup 1.0000x reference)
#include <cuda_runtime.h>
#include <math_constants.h>

#define N_NODES 50000
#define N_EDGES 600000
#define N_REL   64
#define DIM     128
#define DIM4    32     // DIM / 4

// ---------------- device scratch (no allocations allowed) ----------------
__device__ float g_prev[N_NODES * DIM];          // layer-0 output buffer
__device__ int   g_deg[N_NODES];
__device__ int   g_cursor[N_NODES];
__device__ int   g_rowptr[N_NODES + 1];
__device__ int   g_nbr[N_EDGES];                 // CSR-permuted neighbor ids
__device__ int   g_rel[N_EDGES];                 // CSR-permuted relation ids

// ---------------- CSR build ----------------
__global__ void k_zero()
{
    int i = blockIdx.x * blockDim.x + threadIdx.x;
    if (i < N_NODES) { g_deg[i] = 0; g_cursor[i] = 0; }
}

__global__ void k_count(const int* __restrict__ dst)
{
    int e = blockIdx.x * blockDim.x + threadIdx.x;
    if (e < N_EDGES) atomicAdd(&g_deg[dst[e]], 1);
}

// single-block exclusive scan over g_deg -> g_rowptr
__global__ void k_scan()
{
    __shared__ int ssum[1024];
    const int t = threadIdx.x;
    const int C = (N_NODES + 1023) / 1024;   // 49
    int begin  = t * C;
    int finish = begin + C; if (finish > N_NODES) finish = N_NODES;

    int s = 0;
    for (int i = begin; i < finish; ++i) s += g_deg[i];
    ssum[t] = s;
    __syncthreads();
    for (int off = 1; off < 1024; off <<= 1) {
        int v = (t >= off) ? ssum[t - off] : 0;
        __syncthreads();
        ssum[t] += v;
        __syncthreads();
    }
    int run = (t == 0) ? 0 : ssum[t - 1];
    for (int i = begin; i < finish; ++i) { g_rowptr[i] = run; run += g_deg[i]; }
    if (t == 1023) g_rowptr[N_NODES] = ssum[1023];
}

__global__ void k_scatter(const int* __restrict__ dst,
                          const int* __restrict__ nbr,
                          const int* __restrict__ rel)
{
    int e = blockIdx.x * blockDim.x + threadIdx.x;
    if (e < N_EDGES) {
        int d   = dst[e];
        int pos = g_rowptr[d] + atomicAdd(&g_cursor[d], 1);
        g_nbr[pos] = nbr[e];
        g_rel[pos] = rel[e];
    }
}

// ---------------- fused layer kernel: one warp per node ----------------
// score_e = dot(prev[nbr_e], tanh(entity[dst] + relation[rel_e]))
// alpha   = segment softmax (online, single pass)
// neigh   = sum alpha * prev[nbr]
// h       = leaky_relu([prev | neigh] @ W + b); h /= ||h||; no-neighbor -> entity row
__global__ void __launch_bounds__(256)
k_layer(const float* __restrict__ in,
        float*       __restrict__ out,
        const float* __restrict__ entity,
        const float* __restrict__ relation,
        const float* __restrict__ Wl,     // [256,128] row-major
        const float* __restrict__ bl)     // [128]
{
    __shared__ float sh[8][2 * DIM];

    const int wid  = threadIdx.x >> 5;
    const int lane = threadIdx.x & 31;
    const int node = blockIdx.x * 8 + wid;
    if (node >= N_NODES) return;

    const float4* ent4 = (const float4*)entity;
    const float4* in4  = (const float4*)in;
    const float4* rel4 = (const float4*)relation;
    float4*       out4 = (float4*)out;

    float4 ed = ent4[node * DIM4 + lane];           // base embedding of dst (for q)

    const int start = g_rowptr[node];
    const int end   = g_rowptr[node + 1];
    if (start == end) {                              // no neighbors: keep entity row
        out4[node * DIM4 + lane] = ed;
        return;
    }

    float4 pv = in4[node * DIM4 + lane];             // prev[dst]

    // ---- online segment softmax + weighted aggregation ----
    float  m    = -CUDART_INF_F;
    float  dsum = 0.f;
    float4 acc  = make_float4(0.f, 0.f, 0.f, 0.f);

    for (int e = start; e < end; ++e) {
        const int nb = g_nbr[e];
        const int rl = g_rel[e];
        float4 x = in4[nb * DIM4 + lane];
        float4 r = rel4[rl * DIM4 + lane];
        float4 q;
        q.x = tanhf(ed.x + r.x);
        q.y = tanhf(ed.y + r.y);
        q.z = tanhf(ed.z + r.z);
        q.w = tanhf(ed.w + r.w);

        float s = x.x * q.x + x.y * q.y + x.z * q.z + x.w * q.w;
        #pragma unroll
        for (int off = 16; off; off >>= 1)
            s += __shfl_xor_sync(0xffffffffu, s, off);

        if (s > m) {
            float sc = __expf(m - s);   // first edge: exp(-inf)=0, acc/dsum are 0
            acc.x *= sc; acc.y *= sc; acc.z *= sc; acc.w *= sc;
            dsum  *= sc;
            m = s;
        }
        float w = __expf(s - m);
        dsum += w;
        acc.x += w * x.x; acc.y += w * x.y; acc.z += w * x.z; acc.w += w * x.w;
    }

    const float inv = 1.0f / dsum;
    float4 ng = make_float4(acc.x * inv, acc.y * inv, acc.z * inv, acc.w * inv);

    // ---- stage [prev | neigh] into shared for the per-node matmul ----
    float* sv = sh[wid];
    sv[lane * 4 + 0] = pv.x; sv[lane * 4 + 1] = pv.y;
    sv[lane * 4 + 2] = pv.z; sv[lane * 4 + 3] = pv.w;
    sv[DIM + lane * 4 + 0] = ng.x; sv[DIM + lane * 4 + 1] = ng.y;
    sv[DIM + lane * 4 + 2] = ng.z; sv[DIM + lane * 4 + 3] = ng.w;
    __syncwarp();

    // ---- h = v @ W + b  (v: 256, W: 256x128; lane owns cols 4*lane..4*lane+3) ----
    const float4* b4 = (const float4*)bl;
    const float4* W4 = (const float4*)Wl;
    float4 o = b4[lane];
    #pragma unroll 8
    for (int j = 0; j < 2 * DIM; ++j) {
        float  v  = sv[j];                       // SMEM broadcast
        float4 w4 = W4[j * DIM4 + lane];         // L1-resident W stream
        o.x += v * w4.x; o.y += v * w4.y; o.z += v * w4.z; o.w += v * w4.w;
    }

    // LeakyReLU(0.01)
    o.x = (o.x > 0.f) ? o.x : 0.01f * o.x;
    o.y = (o.y > 0.f) ? o.y : 0.01f * o.y;
    o.z = (o.z > 0.f) ? o.z : 0.01f * o.z;
    o.w = (o.w > 0.f) ? o.w : 0.01f * o.w;

    // L2 normalize
    float ss = o.x * o.x + o.y * o.y + o.z * o.z + o.w * o.w;
    #pragma unroll
    for (int off = 16; off; off >>= 1)
        ss += __shfl_xor_sync(0xffffffffu, ss, off);
    float rn = rsqrtf(ss);
    o.x *= rn; o.y *= rn; o.z *= rn; o.w *= rn;

    out4[node * DIM4 + lane] = o;
}

// ---------------- launch ----------------
extern "C" void kernel_launch(void* const* d_in, const int* in_sizes, int n_in,
                              void* d_out, int out_size)
{
    const float* entity   = (const float*)d_in[0];   // [50000,128]
    const float* relation = (const float*)d_in[1];   // [64,128]
    const float* W        = (const float*)d_in[2];   // [2,256,128]
    const float* b        = (const float*)d_in[3];   // [2,128]
    const int*   edst     = (const int*)d_in[4];     // [600000]
    const int*   enbr     = (const int*)d_in[5];
    const int*   erel     = (const int*)d_in[6];
    float*       out      = (float*)d_out;           // [50000,128]

    float* prev = nullptr;
    cudaGetSymbolAddress((void**)&prev, g_prev);

    const int TB = 256;
    k_zero   <<<(N_NODES + TB - 1) / TB, TB>>>();
    k_count  <<<(N_EDGES + TB - 1) / TB, TB>>>(edst);
    k_scan   <<<1, 1024>>>();
    k_scatter<<<(N_EDGES + TB - 1) / TB, TB>>>(edst, enbr, erel);

    const int grid = (N_NODES + 7) / 8;   // 8 warps/block, 1 node/warp
    // layer 0: in = entity_table, out = g_prev
    k_layer<<<grid, TB>>>(entity, prev, entity, relation,
                          W + 0 * 2 * DIM * DIM, b + 0 * DIM);
    // layer 1: in = g_prev, out = d_out
    k_layer<<<grid, TB>>>(prev, out, entity, relation,
                          W + 1 * 2 * DIM * DIM, b + 1 * DIM);
}

// round 2
// speedup vs baseline: 1.7791x; 1.7791x over previous
#include <cuda_runtime.h>
#include <math_constants.h>

#define N_NODES 50000
#define N_EDGES 600000
#define N_REL   64
#define DIM     128
#define DIM4    32     // DIM / 4

typedef unsigned long long ull;

// ---------------- device scratch (no allocations allowed) ----------------
__device__ float g_prev[N_NODES * DIM];          // layer-0 output buffer
__device__ float g_neigh[N_NODES * DIM];         // attention aggregation output
__device__ int   g_deg[N_NODES];
__device__ int   g_cursor[N_NODES];
__device__ int   g_rowptr[N_NODES + 1];
__device__ int   g_nbr[N_EDGES];                 // CSR-permuted neighbor ids
__device__ int   g_rel[N_EDGES];                 // CSR-permuted relation ids

// ---------------- f32x2 helpers (Blackwell packed fp32 pipe) -------------
__device__ __forceinline__ ull dup2(float x) {
    ull r; asm("mov.b64 %0, {%1, %1};" : "=l"(r) : "f"(x)); return r;
}
__device__ __forceinline__ ull ffma2(ull a, ull b, ull c) {
    ull d; asm("fma.rn.f32x2 %0, %1, %2, %3;" : "=l"(d) : "l"(a), "l"(b), "l"(c));
    return d;
}
__device__ __forceinline__ void unpack2(ull v, float& lo, float& hi) {
    asm("mov.b64 {%0, %1}, %2;" : "=f"(lo), "=f"(hi) : "l"(v));
}
__device__ __forceinline__ float tanh_fast(float x) {
    float y; asm("tanh.approx.f32 %0, %1;" : "=f"(y) : "f"(x)); return y;
}

// ---------------- CSR build ----------------
__global__ void k_zero()
{
    int i = blockIdx.x * blockDim.x + threadIdx.x;
    if (i < N_NODES) { g_deg[i] = 0; g_cursor[i] = 0; }
}

__global__ void k_count(const int* __restrict__ dst)
{
    int e = blockIdx.x * blockDim.x + threadIdx.x;
    if (e < N_EDGES) atomicAdd(&g_deg[dst[e]], 1);
}

// single-block exclusive scan over g_deg -> g_rowptr
__global__ void k_scan()
{
    __shared__ int ssum[1024];
    const int t = threadIdx.x;
    const int C = (N_NODES + 1023) / 1024;   // 49
    int begin  = t * C;
    int finish = begin + C; if (finish > N_NODES) finish = N_NODES;

    int s = 0;
    for (int i = begin; i < finish; ++i) s += g_deg[i];
    ssum[t] = s;
    __syncthreads();
    for (int off = 1; off < 1024; off <<= 1) {
        int v = (t >= off) ? ssum[t - off] : 0;
        __syncthreads();
        ssum[t] += v;
        __syncthreads();
    }
    int run = (t == 0) ? 0 : ssum[t - 1];
    for (int i = begin; i < finish; ++i) { g_rowptr[i] = run; run += g_deg[i]; }
    if (t == 1023) g_rowptr[N_NODES] = ssum[1023];
}

__global__ void k_scatter(const int* __restrict__ dst,
                          const int* __restrict__ nbr,
                          const int* __restrict__ rel)
{
    int e = blockIdx.x * blockDim.x + threadIdx.x;
    if (e < N_EDGES) {
        int d   = dst[e];
        int pos = g_rowptr[d] + atomicAdd(&g_cursor[d], 1);
        g_nbr[pos] = nbr[e];
        g_rel[pos] = rel[e];
    }
}

// ---------------- attention kernel: one warp per node ----------------
// score_e = dot(in[nbr_e], tanh(entity[dst] + relation[rel_e]))
// alpha   = segment softmax (online); g_neigh[dst] = sum alpha * in[nbr]
__global__ void __launch_bounds__(256)
k_attn(const float* __restrict__ in,
       const float* __restrict__ entity,
       const float* __restrict__ relation)
{
    const int wid  = threadIdx.x >> 5;
    const int lane = threadIdx.x & 31;
    const int node = blockIdx.x * 8 + wid;
    if (node >= N_NODES) return;

    const int start = g_rowptr[node];
    const int end   = g_rowptr[node + 1];
    if (start == end) return;                       // GEMM epilogue handles deg==0

    const float4* ent4 = (const float4*)entity;
    const float4* in4  = (const float4*)in;
    const float4* rel4 = (const float4*)relation;
    float4*       ng4  = (float4*)g_neigh;

    float4 ed = ent4[node * DIM4 + lane];           // base embedding of dst (for q)

    float  m    = -CUDART_INF_F;
    float  dsum = 0.f;
    float4 acc  = make_float4(0.f, 0.f, 0.f, 0.f);

    for (int e = start; e < end; ++e) {
        const int nb = g_nbr[e];
        const int rl = g_rel[e];
        float4 x = in4[nb * DIM4 + lane];
        float4 r = rel4[rl * DIM4 + lane];
        float4 q;
        q.x = tanh_fast(ed.x + r.x);
        q.y = tanh_fast(ed.y + r.y);
        q.z = tanh_fast(ed.z + r.z);
        q.w = tanh_fast(ed.w + r.w);

        float s = x.x * q.x + x.y * q.y + x.z * q.z + x.w * q.w;
        #pragma unroll
        for (int off = 16; off; off >>= 1)
            s += __shfl_xor_sync(0xffffffffu, s, off);

        if (s > m) {
            float sc = __expf(m - s);   // first edge: exp(-inf)=0, acc/dsum are 0
            acc.x *= sc; acc.y *= sc; acc.z *= sc; acc.w *= sc;
            dsum  *= sc;
            m = s;
        }
        float w = __expf(s - m);
        dsum += w;
        acc.x += w * x.x; acc.y += w * x.y; acc.z += w * x.z; acc.w += w * x.w;
    }

    const float inv = 1.0f / dsum;
    ng4[node * DIM4 + lane] = make_float4(acc.x * inv, acc.y * inv,
                                          acc.z * inv, acc.w * inv);
}

// ---------------- tiled GEMM + epilogue ----------------
// out[m] = select(deg>0, normalize(leaky([in[m] | neigh[m]] @ W + b)), entity[m])
// BM=128 nodes, BN=128 cols (full), BK=32. 256 threads: tx in [0,16) owns 8 cols,
// ty in [0,16) owns 8 rows. fp32x2 packed FMA, pairs along M.
#define PAD_A 132
#define PAD_B 132

__global__ void __launch_bounds__(256)
k_gemm(const float* __restrict__ in,
       const float* __restrict__ neigh,
       const float* __restrict__ Wl,      // [256,128] row-major
       const float* __restrict__ bl,      // [128]
       const float* __restrict__ entity,
       float*       __restrict__ out)
{
    __shared__ float As[32 * PAD_A];      // A^T tile: As[k][m]
    __shared__ float Bs[32 * PAD_B];      // W tile:   Bs[k][n]
    __shared__ float red[128][17];        // row-sum-of-squares partials

    const int t  = threadIdx.x;
    const int tx = t & 15;
    const int ty = t >> 4;
    const int m0 = blockIdx.x * 128;

    ull acc[4][8];
    {
        const float4* b4 = (const float4*)(bl + tx * 8);
        float4 bA = b4[0], bB = b4[1];
        float bv[8] = {bA.x, bA.y, bA.z, bA.w, bB.x, bB.y, bB.z, bB.w};
        #pragma unroll
        for (int mp = 0; mp < 4; ++mp)
            #pragma unroll
            for (int n = 0; n < 8; ++n)
                acc[mp][n] = dup2(bv[n]);
    }

    for (int kc = 0; kc < 8; ++kc) {
        const float* Asrc = (kc < 4) ? in : neigh;
        const int kbase = (kc & 3) * 32;

        // load A tile (128 rows x 32 k), store transposed As[k][m]
        #pragma unroll
        for (int p = 0; p < 4; ++p) {
            int idx = p * 256 + t;
            int r = idx >> 3, q = idx & 7;
            float4 v = make_float4(0.f, 0.f, 0.f, 0.f);
            int node = m0 + r;
            if (node < N_NODES)
                v = *(const float4*)(Asrc + node * DIM + kbase + q * 4);
            int k = q * 4;
            As[(k + 0) * PAD_A + r] = v.x;
            As[(k + 1) * PAD_A + r] = v.y;
            As[(k + 2) * PAD_A + r] = v.z;
            As[(k + 3) * PAD_A + r] = v.w;
        }
        // load W tile (32 k x 128 n)
        #pragma unroll
        for (int p = 0; p < 4; ++p) {
            int idx = p * 256 + t;
            int kr = idx >> 5, nq = idx & 31;
            float4 w = *(const float4*)(Wl + (kc * 32 + kr) * DIM + nq * 4);
            *(float4*)(Bs + kr * PAD_B + nq * 4) = w;
        }
        __syncthreads();

        #pragma unroll 8
        for (int k = 0; k < 32; ++k) {
            const float* arow = As + k * PAD_A + ty * 8;
            ulonglong2 aP0 = *(const ulonglong2*)(arow);
            ulonglong2 aP1 = *(const ulonglong2*)(arow + 4);
            ull ap0 = aP0.x, ap1 = aP0.y, ap2 = aP1.x, ap3 = aP1.y;

            const float* brow = Bs + k * PAD_B + tx * 8;
            float4 b0 = *(const float4*)(brow);
            float4 b1 = *(const float4*)(brow + 4);
            ull bd[8] = {dup2(b0.x), dup2(b0.y), dup2(b0.z), dup2(b0.w),
                         dup2(b1.x), dup2(b1.y), dup2(b1.z), dup2(b1.w)};
            #pragma unroll
            for (int n = 0; n < 8; ++n) {
                acc[0][n] = ffma2(ap0, bd[n], acc[0][n]);
                acc[1][n] = ffma2(ap1, bd[n], acc[1][n]);
                acc[2][n] = ffma2(ap2, bd[n], acc[2][n]);
                acc[3][n] = ffma2(ap3, bd[n], acc[3][n]);
            }
        }
        __syncthreads();
    }

    // epilogue: leaky-relu, L2-normalize per row, deg==0 -> entity row
    float h[8][8];
    #pragma unroll
    for (int mp = 0; mp < 4; ++mp)
        #pragma unroll
        for (int n = 0; n < 8; ++n) {
            float lo, hi;
            unpack2(acc[mp][n], lo, hi);
            h[2 * mp + 0][n] = (lo > 0.f) ? lo : 0.01f * lo;
            h[2 * mp + 1][n] = (hi > 0.f) ? hi : 0.01f * hi;
        }

    #pragma unroll
    for (int i = 0; i < 8; ++i) {
        float s = 0.f;
        #pragma unroll
        for (int n = 0; n < 8; ++n) s += h[i][n] * h[i][n];
        red[ty * 8 + i][tx] = s;
    }
    __syncthreads();

    const float4* ent4 = (const float4*)entity;
    float4*       out4 = (float4*)out;

    #pragma unroll
    for (int i = 0; i < 8; ++i) {
        int node = m0 + ty * 8 + i;
        if (node >= N_NODES) break;
        float s = 0.f;
        #pragma unroll
        for (int j = 0; j < 16; ++j) s += red[ty * 8 + i][j];
        float rn = rsqrtf(s);

        int deg = g_rowptr[node + 1] - g_rowptr[node];
        float4 o0, o1;
        if (deg == 0) {
            o0 = ent4[node * DIM4 + tx * 2];
            o1 = ent4[node * DIM4 + tx * 2 + 1];
        } else {
            o0 = make_float4(h[i][0] * rn, h[i][1] * rn, h[i][2] * rn, h[i][3] * rn);
            o1 = make_float4(h[i][4] * rn, h[i][5] * rn, h[i][6] * rn, h[i][7] * rn);
        }
        out4[node * DIM4 + tx * 2]     = o0;
        out4[node * DIM4 + tx * 2 + 1] = o1;
    }
}

// ---------------- launch ----------------
extern "C" void kernel_launch(void* const* d_in, const int* in_sizes, int n_in,
                              void* d_out, int out_size)
{
    const float* entity   = (const float*)d_in[0];   // [50000,128]
    const float* relation = (const float*)d_in[1];   // [64,128]
    const float* W        = (const float*)d_in[2];   // [2,256,128]
    const float* b        = (const float*)d_in[3];   // [2,128]
    const int*   edst     = (const int*)d_in[4];     // [600000]
    const int*   enbr     = (const int*)d_in[5];
    const int*   erel     = (const int*)d_in[6];
    float*       out      = (float*)d_out;           // [50000,128]

    float* prev  = nullptr;
    float* neigh = nullptr;
    cudaGetSymbolAddress((void**)&prev,  g_prev);
    cudaGetSymbolAddress((void**)&neigh, g_neigh);

    const int TB = 256;
    k_zero   <<<(N_NODES + TB - 1) / TB, TB>>>();
    k_count  <<<(N_EDGES + TB - 1) / TB, TB>>>(edst);
    k_scan   <<<1, 1024>>>();
    k_scatter<<<(N_EDGES + TB - 1) / TB, TB>>>(edst, enbr, erel);

    const int agrid = (N_NODES + 7) / 8;      // 1 node / warp
    const int ggrid = (N_NODES + 127) / 128;  // 128 nodes / block

    // layer 0
    k_attn<<<agrid, TB>>>(entity, entity, relation);
    k_gemm<<<ggrid, TB>>>(entity, neigh, W + 0 * 2 * DIM * DIM, b + 0 * DIM,
                          entity, prev);
    // layer 1
    k_attn<<<agrid, TB>>>(prev, entity, relation);
    k_gemm<<<ggrid, TB>>>(prev, neigh, W + 1 * 2 * DIM * DIM, b + 1 * DIM,
                          entity, out);
}

// round 5
// speedup vs baseline: 2.1378x; 1.2017x over previous
#include <cuda_runtime.h>
#include <cuda_bf16.h>
#include <math_constants.h>
#include <cstdint>
#include <mma.h>

using namespace nvcuda;

#define N_NODES 50000
#define N_EDGES 600000
#define N_REL   64
#define DIM     128
#define DIM4    32

typedef unsigned long long ull;

// ---------------- device scratch (no allocations allowed) ----------------
__device__ float g_prev[N_NODES * DIM];
__device__ float g_neigh[N_NODES * DIM];
__device__ int   g_deg[N_NODES];
__device__ int   g_cursor[N_NODES];
__device__ int   g_rowptr[N_NODES + 1];
__device__ int   g_nbr[N_EDGES];
__device__ int   g_rel[N_EDGES];
// W pre-transposed-free: plain [k][n] row-major bf16, hi tile then lo tile.
// [layer][k-chunk] -> 64KB blob: 32KB hi (128x128 bf16) + 32KB lo
__device__ __align__(16) unsigned char g_Wsw[2][2][65536];

__device__ __forceinline__ float tanh_fast(float x) {
    float y; asm("tanh.approx.f32 %0, %1;" : "=f"(y) : "f"(x)); return y;
}

// ---------------- CSR build ----------------
__global__ void k_zero()
{
    int i = blockIdx.x * blockDim.x + threadIdx.x;
    if (i < N_NODES) { g_deg[i] = 0; g_cursor[i] = 0; }
}
__global__ void k_count(const int* __restrict__ dst)
{
    int e = blockIdx.x * blockDim.x + threadIdx.x;
    if (e < N_EDGES) atomicAdd(&g_deg[dst[e]], 1);
}
__global__ void k_scan()
{
    __shared__ int ssum[1024];
    const int t = threadIdx.x;
    const int C = (N_NODES + 1023) / 1024;
    int begin = t * C, finish = begin + C;
    if (finish > N_NODES) finish = N_NODES;
    int s = 0;
    for (int i = begin; i < finish; ++i) s += g_deg[i];
    ssum[t] = s;
    __syncthreads();
    for (int off = 1; off < 1024; off <<= 1) {
        int v = (t >= off) ? ssum[t - off] : 0;
        __syncthreads();
        ssum[t] += v;
        __syncthreads();
    }
    int run = (t == 0) ? 0 : ssum[t - 1];
    for (int i = begin; i < finish; ++i) { g_rowptr[i] = run; run += g_deg[i]; }
    if (t == 1023) g_rowptr[N_NODES] = ssum[1023];
}
__global__ void k_scatter(const int* __restrict__ dst,
                          const int* __restrict__ nbr,
                          const int* __restrict__ rel)
{
    int e = blockIdx.x * blockDim.x + threadIdx.x;
    if (e < N_EDGES) {
        int d   = dst[e];
        int pos = g_rowptr[d] + atomicAdd(&g_cursor[d], 1);
        g_nbr[pos] = nbr[e];
        g_rel[pos] = rel[e];
    }
}

// ---------------- W bf16 hi/lo split (once). blob[kc]: hi[k][n], lo[k][n] ----
__global__ void k_wconv(const float* __restrict__ W)
{
    int idx = blockIdx.x * blockDim.x + threadIdx.x;  // 2*2*128*128 = 65536
    if (idx >= 2 * 2 * 128 * 128) return;
    int l  = idx >> 15;
    int r  = idx & 32767;
    int kc = r >> 14; r &= 16383;
    int k  = r >> 7;
    int n  = r & 127;
    float w = W[(l * 256 + kc * 128 + k) * 128 + n];
    __nv_bfloat16 hi = __float2bfloat16(w);
    __nv_bfloat16 lo = __float2bfloat16(w - __bfloat162float(hi));
    __nv_bfloat16* base = (__nv_bfloat16*)&g_Wsw[l][kc][0];
    base[k * 128 + n]         = hi;
    base[16384 + k * 128 + n] = lo;
}

// ---------------- attention: one warp per node, pipelined edge loop --------
__global__ void __launch_bounds__(256)
k_attn(const float* __restrict__ in,
       const float* __restrict__ entity,
       const float* __restrict__ relation)
{
    const int wid  = threadIdx.x >> 5;
    const int lane = threadIdx.x & 31;
    const int node = blockIdx.x * 8 + wid;
    if (node >= N_NODES) return;

    const int start = g_rowptr[node];
    const int end   = g_rowptr[node + 1];
    if (start == end) return;

    const float4* ent4 = (const float4*)entity;
    const float4* in4  = (const float4*)in;
    const float4* rel4 = (const float4*)relation;
    float4*       ng4  = (float4*)g_neigh;

    float4 ed = ent4[node * DIM4 + lane];

    float  m    = -CUDART_INF_F;
    float  dsum = 0.f;
    float4 acc  = make_float4(0.f, 0.f, 0.f, 0.f);

    int nb = g_nbr[start];
    int rl = g_rel[start];
    float4 x = in4[nb * DIM4 + lane];
    float4 r = rel4[rl * DIM4 + lane];

    for (int e = start; e < end; ++e) {
        float4 xc = x, rc = r;
        if (e + 1 < end) {                  // prefetch next edge before the chain
            int nb2 = g_nbr[e + 1];
            int rl2 = g_rel[e + 1];
            x = in4[nb2 * DIM4 + lane];
            r = rel4[rl2 * DIM4 + lane];
        }
        float4 q;
        q.x = tanh_fast(ed.x + rc.x);
        q.y = tanh_fast(ed.y + rc.y);
        q.z = tanh_fast(ed.z + rc.z);
        q.w = tanh_fast(ed.w + rc.w);

        float s = xc.x * q.x + xc.y * q.y + xc.z * q.z + xc.w * q.w;
        #pragma unroll
        for (int off = 16; off; off >>= 1)
            s += __shfl_xor_sync(0xffffffffu, s, off);

        if (s > m) {
            float sc = __expf(m - s);
            acc.x *= sc; acc.y *= sc; acc.z *= sc; acc.w *= sc;
            dsum  *= sc;
            m = s;
        }
        float w = __expf(s - m);
        dsum += w;
        acc.x += w * xc.x; acc.y += w * xc.y; acc.z += w * xc.z; acc.w += w * xc.w;
    }

    const float inv = 1.0f / dsum;
    ng4[node * DIM4 + lane] = make_float4(acc.x * inv, acc.y * inv,
                                          acc.z * inv, acc.w * inv);
}

// ---------------- WMMA bf16x3 GEMM + epilogue ----------------
// per block: 128 nodes x 128 cols; K=256 in two 128-chunks (in, then neigh).
// 8 warps: warp_m = wid>>2 (64 rows), warp_n = wid&3 (32 cols).
// D += Ahi*Bhi + Ahi*Blo + Alo*Bhi  (f32 accumulate)
#define AS_STRIDE 136                       // bf16 elems per row (pad 8)
#define CS_STRIDE 132                       // f32 elems per row (pad 4)
#define SM_BIAS   0
#define SM_A_HI   1024
#define SM_A_LO   (SM_A_HI + 128 * AS_STRIDE * 2)       // +34816
#define SM_B_HI   (SM_A_LO + 128 * AS_STRIDE * 2)
#define SM_B_LO   (SM_B_HI + 128 * AS_STRIDE * 2)
#define SM_C      1024                      // reuses A region (67584 <= 69632)
#define SMEM_TOTAL (SM_B_LO + 128 * AS_STRIDE * 2)      // 140288

__global__ void __launch_bounds__(256, 1)
k_mma(const float* __restrict__ in,
      const float* __restrict__ neigh,
      const unsigned char* __restrict__ wsw,   // g_Wsw[layer]: 2 x 64KB blobs
      const float* __restrict__ bl,
      const float* __restrict__ entity,
      float*       __restrict__ out)
{
    extern __shared__ unsigned char smem[];
    const int t      = threadIdx.x;
    const int wid    = t >> 5;
    const int warp_m = wid >> 2;         // 0..1
    const int warp_n = wid & 3;          // 0..3
    const int m0     = blockIdx.x * 128;

    float* sbias = (float*)(smem + SM_BIAS);
    if (t < 128) sbias[t] = bl[t];

    __nv_bfloat16* Ah = (__nv_bfloat16*)(smem + SM_A_HI);
    __nv_bfloat16* Al = (__nv_bfloat16*)(smem + SM_A_LO);
    __nv_bfloat16* Bh = (__nv_bfloat16*)(smem + SM_B_HI);
    __nv_bfloat16* Bl = (__nv_bfloat16*)(smem + SM_B_LO);

    wmma::fragment<wmma::accumulator, 16, 16, 16, float> c[4][2];
    #pragma unroll
    for (int mt = 0; mt < 4; ++mt)
        #pragma unroll
        for (int nt = 0; nt < 2; ++nt)
            wmma::fill_fragment(c[mt][nt], 0.f);

    for (int kc = 0; kc < 2; ++kc) {
        const float* Asrc = kc ? neigh : in;
        __syncthreads();    // previous chunk's MMA reads done before overwrite

        // A chunk [128 x 128] fp32 -> bf16 hi/lo into padded smem
        #pragma unroll
        for (int p = 0; p < 16; ++p) {
            int f   = p * 256 + t;           // 4096 float4
            int row = f >> 5;
            int c4  = f & 31;
            int node = m0 + row;
            float4 v = make_float4(0.f, 0.f, 0.f, 0.f);
            if (node < N_NODES)
                v = *(const float4*)(Asrc + node * DIM + c4 * 4);

            __nv_bfloat16 h0 = __float2bfloat16(v.x);
            __nv_bfloat16 h1 = __float2bfloat16(v.y);
            __nv_bfloat16 h2 = __float2bfloat16(v.z);
            __nv_bfloat16 h3 = __float2bfloat16(v.w);
            __nv_bfloat16 l0 = __float2bfloat16(v.x - __bfloat162float(h0));
            __nv_bfloat16 l1 = __float2bfloat16(v.y - __bfloat162float(h1));
            __nv_bfloat16 l2 = __float2bfloat16(v.z - __bfloat162float(h2));
            __nv_bfloat16 l3 = __float2bfloat16(v.w - __bfloat162float(h3));

            ull ph = (ull)__bfloat16_as_ushort(h0)
                   | ((ull)__bfloat16_as_ushort(h1) << 16)
                   | ((ull)__bfloat16_as_ushort(h2) << 32)
                   | ((ull)__bfloat16_as_ushort(h3) << 48);
            ull pl = (ull)__bfloat16_as_ushort(l0)
                   | ((ull)__bfloat16_as_ushort(l1) << 16)
                   | ((ull)__bfloat16_as_ushort(l2) << 32)
                   | ((ull)__bfloat16_as_ushort(l3) << 48);

            int eo = row * AS_STRIDE + c4 * 4;
            *(ull*)(Ah + eo) = ph;
            *(ull*)(Al + eo) = pl;
        }
        // B chunk: copy pre-split bf16 [128k x 128n] into padded smem
        {
            const uint32_t* sh = (const uint32_t*)(wsw + kc * 65536);
            const uint32_t* sl = (const uint32_t*)(wsw + kc * 65536 + 32768);
            #pragma unroll
            for (int p = 0; p < 32; ++p) {
                int idx = p * 256 + t;       // 8192 uint32 per tile
                int row = idx >> 6;
                int cp  = idx & 63;          // bf16 pair
                int eo  = row * AS_STRIDE + cp * 2;
                *(uint32_t*)(Bh + eo) = sh[idx];
                *(uint32_t*)(Bl + eo) = sl[idx];
            }
        }
        __syncthreads();

        #pragma unroll
        for (int ks = 0; ks < 8; ++ks) {
            wmma::fragment<wmma::matrix_b, 16, 16, 16, __nv_bfloat16,
                           wmma::row_major> bh[2], blo[2];
            #pragma unroll
            for (int nt = 0; nt < 2; ++nt) {
                int ncol = warp_n * 32 + nt * 16;
                wmma::load_matrix_sync(bh[nt],  Bh + ks * 16 * AS_STRIDE + ncol,
                                       AS_STRIDE);
                wmma::load_matrix_sync(blo[nt], Bl + ks * 16 * AS_STRIDE + ncol,
                                       AS_STRIDE);
            }
            #pragma unroll
            for (int mt = 0; mt < 4; ++mt) {
                int mrow = warp_m * 64 + mt * 16;
                wmma::fragment<wmma::matrix_a, 16, 16, 16, __nv_bfloat16,
                               wmma::row_major> ah, alo;
                wmma::load_matrix_sync(ah,  Ah + mrow * AS_STRIDE + ks * 16,
                                       AS_STRIDE);
                wmma::load_matrix_sync(alo, Al + mrow * AS_STRIDE + ks * 16,
                                       AS_STRIDE);
                #pragma unroll
                for (int nt = 0; nt < 2; ++nt) {
                    wmma::mma_sync(c[mt][nt], ah,  bh[nt],  c[mt][nt]);
                    wmma::mma_sync(c[mt][nt], ah,  blo[nt], c[mt][nt]);
                    wmma::mma_sync(c[mt][nt], alo, bh[nt],  c[mt][nt]);
                }
            }
        }
    }
    __syncthreads();    // all MMA smem reads done before C overwrites A region

    // store accumulators to smem (row-major, padded)
    float* Cs = (float*)(smem + SM_C);
    #pragma unroll
    for (int mt = 0; mt < 4; ++mt)
        #pragma unroll
        for (int nt = 0; nt < 2; ++nt)
            wmma::store_matrix_sync(Cs + (warp_m * 64 + mt * 16) * CS_STRIDE
                                       + warp_n * 32 + nt * 16,
                                    c[mt][nt], CS_STRIDE, wmma::mem_row_major);
    __syncthreads();

    // epilogue: 2 threads per row (64 cols each): bias + leaky + L2 norm
    {
        const int r    = t >> 1;
        const int half = t & 1;
        const int node = m0 + r;
        const float* crow = Cs + r * CS_STRIDE + half * 64;
        const float* brow = sbias + half * 64;

        float sq = 0.f;
        #pragma unroll
        for (int j = 0; j < 64; ++j) {
            float v = crow[j] + brow[j];
            v = (v > 0.f) ? v : 0.01f * v;
            sq += v * v;
        }
        sq += __shfl_xor_sync(0xffffffffu, sq, 1);
        float rn = rsqrtf(sq);

        if (node < N_NODES) {
            int deg = g_rowptr[node + 1] - g_rowptr[node];
            float4*       out4 = (float4*)out;
            const float4* ent4 = (const float4*)entity;
            #pragma unroll
            for (int j4 = 0; j4 < 16; ++j4) {
                float4 o;
                if (deg == 0) {
                    o = ent4[node * DIM4 + half * 16 + j4];
                } else {
                    float v0 = crow[j4 * 4 + 0] + brow[j4 * 4 + 0];
                    float v1 = crow[j4 * 4 + 1] + brow[j4 * 4 + 1];
                    float v2 = crow[j4 * 4 + 2] + brow[j4 * 4 + 2];
                    float v3 = crow[j4 * 4 + 3] + brow[j4 * 4 + 3];
                    o.x = ((v0 > 0.f) ? v0 : 0.01f * v0) * rn;
                    o.y = ((v1 > 0.f) ? v1 : 0.01f * v1) * rn;
                    o.z = ((v2 > 0.f) ? v2 : 0.01f * v2) * rn;
                    o.w = ((v3 > 0.f) ? v3 : 0.01f * v3) * rn;
                }
                out4[node * DIM4 + half * 16 + j4] = o;
            }
        }
    }
}

// ---------------- launch ----------------
extern "C" void kernel_launch(void* const* d_in, const int* in_sizes, int n_in,
                              void* d_out, int out_size)
{
    const float* entity   = (const float*)d_in[0];
    const float* relation = (const float*)d_in[1];
    const float* W        = (const float*)d_in[2];
    const float* b        = (const float*)d_in[3];
    const int*   edst     = (const int*)d_in[4];
    const int*   enbr     = (const int*)d_in[5];
    const int*   erel     = (const int*)d_in[6];
    float*       out      = (float*)d_out;

    float* prev  = nullptr;
    float* neigh = nullptr;
    unsigned char* wsw = nullptr;
    cudaGetSymbolAddress((void**)&prev,  g_prev);
    cudaGetSymbolAddress((void**)&neigh, g_neigh);
    cudaGetSymbolAddress((void**)&wsw,   g_Wsw);

    cudaFuncSetAttribute(k_mma, cudaFuncAttributeMaxDynamicSharedMemorySize,
                         SMEM_TOTAL);

    const int TB = 256;
    k_wconv  <<<(2 * 2 * 128 * 128 + TB - 1) / TB, TB>>>(W);
    k_zero   <<<(N_NODES + TB - 1) / TB, TB>>>();
    k_count  <<<(N_EDGES + TB - 1) / TB, TB>>>(edst);
    k_scan   <<<1, 1024>>>();
    k_scatter<<<(N_EDGES + TB - 1) / TB, TB>>>(edst, enbr, erel);

    const int agrid = (N_NODES + 7) / 8;
    const int ggrid = (N_NODES + 127) / 128;

    // layer 0
    k_attn<<<agrid, TB>>>(entity, entity, relation);
    k_mma <<<ggrid, TB, SMEM_TOTAL>>>(entity, neigh, wsw + 0 * 2 * 65536,
                                      b + 0 * DIM, entity, prev);
    // layer 1
    k_attn<<<agrid, TB>>>(prev, entity, relation);
    k_mma <<<ggrid, TB, SMEM_TOTAL>>>(prev, neigh, wsw + 1 * 2 * 65536,
                                      b + 1 * DIM, entity, out);
}

// round 6
// speedup vs baseline: 2.2671x; 1.0605x over previous
#include <cuda_runtime.h>
#include <cuda_bf16.h>
#include <math_constants.h>
#include <cstdint>
#include <mma.h>

using namespace nvcuda;

#define N_NODES 50000
#define N_EDGES 600000
#define N_REL   64
#define DIM     128
#define DIM4    32

#define SCAN_B 1024
#define SCAN_G ((N_NODES + SCAN_B - 1) / SCAN_B)   // 49

typedef unsigned long long ull;

// ---------------- device scratch (no allocations allowed) ----------------
__device__ float g_prev[N_NODES * DIM];
__device__ float g_neigh[N_NODES * DIM];
__device__ int   g_deg[N_NODES];
__device__ int   g_cursor[N_NODES];
__device__ int   g_rowptr[N_NODES + 1];
__device__ int   g_part[SCAN_G];
__device__ int   g_nbr[N_EDGES];
__device__ int   g_rel[N_EDGES];
// W split: [layer][k-chunk] -> 64KB blob: 32KB hi (128x128 bf16 [k][n]) + 32KB lo
__device__ __align__(16) unsigned char g_Wsw[2][2][65536];

__device__ __forceinline__ float tanh_fast(float x) {
    float y; asm("tanh.approx.f32 %0, %1;" : "=f"(y) : "f"(x)); return y;
}

// ---------------- CSR build ----------------
__global__ void k_zero()
{
    int i = blockIdx.x * blockDim.x + threadIdx.x;
    if (i < N_NODES) { g_deg[i] = 0; g_cursor[i] = 0; }
}
__global__ void k_count(const int* __restrict__ dst)
{
    int e = blockIdx.x * blockDim.x + threadIdx.x;
    if (e < N_EDGES) atomicAdd(&g_deg[dst[e]], 1);
}

// phase 1: block-local exclusive scan (coalesced) + block partial sums
__global__ void k_scan1()
{
    __shared__ int warpsum[32];
    const int lane = threadIdx.x & 31;
    const int wid  = threadIdx.x >> 5;
    const int i    = blockIdx.x * SCAN_B + threadIdx.x;

    int v = (i < N_NODES) ? g_deg[i] : 0;
    int s = v;
    #pragma unroll
    for (int o = 1; o < 32; o <<= 1) {
        int u = __shfl_up_sync(0xffffffffu, s, o);
        if (lane >= o) s += u;
    }
    if (lane == 31) warpsum[wid] = s;
    __syncthreads();
    if (wid == 0) {
        int ws = warpsum[lane];
        #pragma unroll
        for (int o = 1; o < 32; o <<= 1) {
            int u = __shfl_up_sync(0xffffffffu, ws, o);
            if (lane >= o) ws += u;
        }
        warpsum[lane] = ws;
    }
    __syncthreads();
    int incl = s + (wid ? warpsum[wid - 1] : 0);
    if (i < N_NODES) g_rowptr[i] = incl - v;        // local exclusive
    if (threadIdx.x == SCAN_B - 1) g_part[blockIdx.x] = incl;
}
// phase 2: scan the 49 partials (one tiny block)
__global__ void k_scan2()
{
    __shared__ int sp[64];
    const int t = threadIdx.x;                       // 64 threads
    sp[t] = (t < SCAN_G) ? g_part[t] : 0;
    __syncthreads();
    #pragma unroll
    for (int o = 1; o < 64; o <<= 1) {
        int u = (t >= o) ? sp[t - o] : 0;
        __syncthreads();
        sp[t] += u;
        __syncthreads();
    }
    if (t < SCAN_G) g_part[t] = (t == 0) ? 0 : sp[t - 1];
    if (t == 63) g_rowptr[N_NODES] = sp[SCAN_G - 1];
}
// phase 3: add block offsets (coalesced)
__global__ void k_scan3()
{
    int i = blockIdx.x * SCAN_B + threadIdx.x;
    if (i < N_NODES) g_rowptr[i] += g_part[blockIdx.x];
}

__global__ void k_scatter(const int* __restrict__ dst,
                          const int* __restrict__ nbr,
                          const int* __restrict__ rel)
{
    int e = blockIdx.x * blockDim.x + threadIdx.x;
    if (e < N_EDGES) {
        int d   = dst[e];
        int pos = g_rowptr[d] + atomicAdd(&g_cursor[d], 1);
        g_nbr[pos] = nbr[e];
        g_rel[pos] = rel[e];
    }
}

// ---------------- W bf16 hi/lo split (once). blob[kc]: hi[k][n], lo[k][n] ----
__global__ void k_wconv(const float* __restrict__ W)
{
    int idx = blockIdx.x * blockDim.x + threadIdx.x;  // 2*2*128*128 = 65536
    if (idx >= 2 * 2 * 128 * 128) return;
    int l  = idx >> 15;
    int r  = idx & 32767;
    int kc = r >> 14; r &= 16383;
    int k  = r >> 7;
    int n  = r & 127;
    float w = W[(l * 256 + kc * 128 + k) * 128 + n];
    __nv_bfloat16 hi = __float2bfloat16(w);
    __nv_bfloat16 lo = __float2bfloat16(w - __bfloat162float(hi));
    __nv_bfloat16* base = (__nv_bfloat16*)&g_Wsw[l][kc][0];
    base[k * 128 + n]         = hi;
    base[16384 + k * 128 + n] = lo;
}

// ---------------- attention: one warp per node, pipelined edge loop --------
__global__ void __launch_bounds__(256)
k_attn(const float* __restrict__ in,
       const float* __restrict__ entity,
       const float* __restrict__ relation)
{
    const int wid  = threadIdx.x >> 5;
    const int lane = threadIdx.x & 31;
    const int node = blockIdx.x * 8 + wid;
    if (node >= N_NODES) return;

    const int start = g_rowptr[node];
    const int end   = g_rowptr[node + 1];
    if (start == end) return;

    const float4* ent4 = (const float4*)entity;
    const float4* in4  = (const float4*)in;
    const float4* rel4 = (const float4*)relation;
    float4*       ng4  = (float4*)g_neigh;

    float4 ed = ent4[node * DIM4 + lane];

    float  m    = -CUDART_INF_F;
    float  dsum = 0.f;
    float4 acc  = make_float4(0.f, 0.f, 0.f, 0.f);

    int nb = g_nbr[start];
    int rl = g_rel[start];
    float4 x = in4[nb * DIM4 + lane];
    float4 r = rel4[rl * DIM4 + lane];

    for (int e = start; e < end; ++e) {
        float4 xc = x, rc = r;
        if (e + 1 < end) {                  // prefetch next edge before the chain
            int nb2 = g_nbr[e + 1];
            int rl2 = g_rel[e + 1];
            x = in4[nb2 * DIM4 + lane];
            r = rel4[rl2 * DIM4 + lane];
        }
        float4 q;
        q.x = tanh_fast(ed.x + rc.x);
        q.y = tanh_fast(ed.y + rc.y);
        q.z = tanh_fast(ed.z + rc.z);
        q.w = tanh_fast(ed.w + rc.w);

        float s = xc.x * q.x + xc.y * q.y + xc.z * q.z + xc.w * q.w;
        #pragma unroll
        for (int off = 16; off; off >>= 1)
            s += __shfl_xor_sync(0xffffffffu, s, off);

        if (s > m) {
            float sc = __expf(m - s);
            acc.x *= sc; acc.y *= sc; acc.z *= sc; acc.w *= sc;
            dsum  *= sc;
            m = s;
        }
        float w = __expf(s - m);
        dsum += w;
        acc.x += w * xc.x; acc.y += w * xc.y; acc.z += w * xc.z; acc.w += w * xc.w;
    }

    const float inv = 1.0f / dsum;
    ng4[node * DIM4 + lane] = make_float4(acc.x * inv, acc.y * inv,
                                          acc.z * inv, acc.w * inv);
}

// ---------------- WMMA bf16x3 GEMM + epilogue ----------------
// per block: 128 nodes x 128 cols; K=256 in two 128-chunks (in, then neigh).
// 8 warps: warp_m = wid>>2 (64 rows), warp_n = wid&3 (32 cols).
// D += Ahi*Bhi + Ahi*Blo + Alo*Bhi  (f32 accumulate)
// A staged in smem (bf16 hi/lo); B fragments loaded straight from the
// L1-resident global W blob -> smem drops to ~69KB -> 2 blocks/SM.
#define AS_STRIDE 136                       // bf16 elems per row (pad 8)
#define CS_STRIDE 132                       // f32 elems per row (pad 4)
#define SM_BIAS   0
#define SM_A_HI   1024
#define SM_A_LO   (SM_A_HI + 128 * AS_STRIDE * 2)       // 35840
#define SM_C      1024                      // reuses A region after MMA
#define SMEM_TOTAL (SM_A_LO + 128 * AS_STRIDE * 2)      // 70656

__global__ void __launch_bounds__(256, 2)
k_mma(const float* __restrict__ in,
      const float* __restrict__ neigh,
      const unsigned char* __restrict__ wsw,   // g_Wsw[layer]: 2 x 64KB blobs
      const float* __restrict__ bl,
      const float* __restrict__ entity,
      float*       __restrict__ out)
{
    extern __shared__ unsigned char smem[];
    const int t      = threadIdx.x;
    const int wid    = t >> 5;
    const int warp_m = wid >> 2;         // 0..1
    const int warp_n = wid & 3;          // 0..3
    const int m0     = blockIdx.x * 128;

    float* sbias = (float*)(smem + SM_BIAS);
    if (t < 128) sbias[t] = bl[t];

    __nv_bfloat16* Ah = (__nv_bfloat16*)(smem + SM_A_HI);
    __nv_bfloat16* Al = (__nv_bfloat16*)(smem + SM_A_LO);

    wmma::fragment<wmma::accumulator, 16, 16, 16, float> c[4][2];
    #pragma unroll
    for (int mt = 0; mt < 4; ++mt)
        #pragma unroll
        for (int nt = 0; nt < 2; ++nt)
            wmma::fill_fragment(c[mt][nt], 0.f);

    for (int kc = 0; kc < 2; ++kc) {
        const float* Asrc = kc ? neigh : in;
        __syncthreads();    // previous chunk's MMA reads done before overwrite

        // A chunk [128 x 128] fp32 -> bf16 hi/lo into padded smem
        #pragma unroll
        for (int p = 0; p < 16; ++p) {
            int f   = p * 256 + t;           // 4096 float4
            int row = f >> 5;
            int c4  = f & 31;
            int node = m0 + row;
            float4 v = make_float4(0.f, 0.f, 0.f, 0.f);
            if (node < N_NODES)
                v = *(const float4*)(Asrc + node * DIM + c4 * 4);

            __nv_bfloat16 h0 = __float2bfloat16(v.x);
            __nv_bfloat16 h1 = __float2bfloat16(v.y);
            __nv_bfloat16 h2 = __float2bfloat16(v.z);
            __nv_bfloat16 h3 = __float2bfloat16(v.w);
            __nv_bfloat16 l0 = __float2bfloat16(v.x - __bfloat162float(h0));
            __nv_bfloat16 l1 = __float2bfloat16(v.y - __bfloat162float(h1));
            __nv_bfloat16 l2 = __float2bfloat16(v.z - __bfloat162float(h2));
            __nv_bfloat16 l3 = __float2bfloat16(v.w - __bfloat162float(h3));

            ull ph = (ull)__bfloat16_as_ushort(h0)
                   | ((ull)__bfloat16_as_ushort(h1) << 16)
                   | ((ull)__bfloat16_as_ushort(h2) << 32)
                   | ((ull)__bfloat16_as_ushort(h3) << 48);
            ull pl = (ull)__bfloat16_as_ushort(l0)
                   | ((ull)__bfloat16_as_ushort(l1) << 16)
                   | ((ull)__bfloat16_as_ushort(l2) << 32)
                   | ((ull)__bfloat16_as_ushort(l3) << 48);

            int eo = row * AS_STRIDE + c4 * 4;
            *(ull*)(Ah + eo) = ph;
            *(ull*)(Al + eo) = pl;
        }
        __syncthreads();

        const __nv_bfloat16* Bh = (const __nv_bfloat16*)(wsw + kc * 65536);
        const __nv_bfloat16* Bl = (const __nv_bfloat16*)(wsw + kc * 65536 + 32768);

        #pragma unroll
        for (int ks = 0; ks < 8; ++ks) {
            wmma::fragment<wmma::matrix_b, 16, 16, 16, __nv_bfloat16,
                           wmma::row_major> bh[2], blo[2];
            #pragma unroll
            for (int nt = 0; nt < 2; ++nt) {
                int ncol = warp_n * 32 + nt * 16;
                wmma::load_matrix_sync(bh[nt],  Bh + ks * 16 * 128 + ncol, 128);
                wmma::load_matrix_sync(blo[nt], Bl + ks * 16 * 128 + ncol, 128);
            }
            #pragma unroll
            for (int mt = 0; mt < 4; ++mt) {
                int mrow = warp_m * 64 + mt * 16;
                wmma::fragment<wmma::matrix_a, 16, 16, 16, __nv_bfloat16,
                               wmma::row_major> ah, alo;
                wmma::load_matrix_sync(ah,  Ah + mrow * AS_STRIDE + ks * 16,
                                       AS_STRIDE);
                wmma::load_matrix_sync(alo, Al + mrow * AS_STRIDE + ks * 16,
                                       AS_STRIDE);
                #pragma unroll
                for (int nt = 0; nt < 2; ++nt) {
                    wmma::mma_sync(c[mt][nt], ah,  bh[nt],  c[mt][nt]);
                    wmma::mma_sync(c[mt][nt], ah,  blo[nt], c[mt][nt]);
                    wmma::mma_sync(c[mt][nt], alo, bh[nt],  c[mt][nt]);
                }
            }
        }
    }
    __syncthreads();    // all MMA smem reads done before C overwrites A region

    // store accumulators to smem (row-major, padded)
    float* Cs = (float*)(smem + SM_C);
    #pragma unroll
    for (int mt = 0; mt < 4; ++mt)
        #pragma unroll
        for (int nt = 0; nt < 2; ++nt)
            wmma::store_matrix_sync(Cs + (warp_m * 64 + mt * 16) * CS_STRIDE
                                       + warp_n * 32 + nt * 16,
                                    c[mt][nt], CS_STRIDE, wmma::mem_row_major);
    __syncthreads();

    // epilogue: 2 threads per row (64 cols each): bias + leaky + L2 norm
    {
        const int r    = t >> 1;
        const int half = t & 1;
        const int node = m0 + r;
        const float* crow = Cs + r * CS_STRIDE + half * 64;
        const float* brow = sbias + half * 64;

        float sq = 0.f;
        #pragma unroll
        for (int j = 0; j < 64; ++j) {
            float v = crow[j] + brow[j];
            v = (v > 0.f) ? v : 0.01f * v;
            sq += v * v;
        }
        sq += __shfl_xor_sync(0xffffffffu, sq, 1);
        float rn = rsqrtf(sq);

        if (node < N_NODES) {
            int deg = g_rowptr[node + 1] - g_rowptr[node];
            float4*       out4 = (float4*)out;
            const float4* ent4 = (const float4*)entity;
            #pragma unroll
            for (int j4 = 0; j4 < 16; ++j4) {
                float4 o;
                if (deg == 0) {
                    o = ent4[node * DIM4 + half * 16 + j4];
                } else {
                    float v0 = crow[j4 * 4 + 0] + brow[j4 * 4 + 0];
                    float v1 = crow[j4 * 4 + 1] + brow[j4 * 4 + 1];
                    float v2 = crow[j4 * 4 + 2] + brow[j4 * 4 + 2];
                    float v3 = crow[j4 * 4 + 3] + brow[j4 * 4 + 3];
                    o.x = ((v0 > 0.f) ? v0 : 0.01f * v0) * rn;
                    o.y = ((v1 > 0.f) ? v1 : 0.01f * v1) * rn;
                    o.z = ((v2 > 0.f) ? v2 : 0.01f * v2) * rn;
                    o.w = ((v3 > 0.f) ? v3 : 0.01f * v3) * rn;
                }
                out4[node * DIM4 + half * 16 + j4] = o;
            }
        }
    }
}

// ---------------- launch ----------------
extern "C" void kernel_launch(void* const* d_in, const int* in_sizes, int n_in,
                              void* d_out, int out_size)
{
    const float* entity   = (const float*)d_in[0];
    const float* relation = (const float*)d_in[1];
    const float* W        = (const float*)d_in[2];
    const float* b        = (const float*)d_in[3];
    const int*   edst     = (const int*)d_in[4];
    const int*   enbr     = (const int*)d_in[5];
    const int*   erel     = (const int*)d_in[6];
    float*       out      = (float*)d_out;

    float* prev  = nullptr;
    float* neigh = nullptr;
    unsigned char* wsw = nullptr;
    cudaGetSymbolAddress((void**)&prev,  g_prev);
    cudaGetSymbolAddress((void**)&neigh, g_neigh);
    cudaGetSymbolAddress((void**)&wsw,   g_Wsw);

    cudaFuncSetAttribute(k_mma, cudaFuncAttributeMaxDynamicSharedMemorySize,
                         SMEM_TOTAL);

    const int TB = 256;
    k_wconv  <<<(2 * 2 * 128 * 128 + TB - 1) / TB, TB>>>(W);
    k_zero   <<<(N_NODES + TB - 1) / TB, TB>>>();
    k_count  <<<(N_EDGES + TB - 1) / TB, TB>>>(edst);
    k_scan1  <<<SCAN_G, SCAN_B>>>();
    k_scan2  <<<1, 64>>>();
    k_scan3  <<<SCAN_G, SCAN_B>>>();
    k_scatter<<<(N_EDGES + TB - 1) / TB, TB>>>(edst, enbr, erel);

    const int agrid = (N_NODES + 7) / 8;
    const int ggrid = (N_NODES + 127) / 128;

    // layer 0
    k_attn<<<agrid, TB>>>(entity, entity, relation);
    k_mma <<<ggrid, TB, SMEM_TOTAL>>>(entity, neigh, wsw + 0 * 2 * 65536,
                                      b + 0 * DIM, entity, prev);
    // layer 1
    k_attn<<<agrid, TB>>>(prev, entity, relation);
    k_mma <<<ggrid, TB, SMEM_TOTAL>>>(prev, neigh, wsw + 1 * 2 * 65536,
                                      b + 1 * DIM, entity, out);
}